// round 9
// baseline (speedup 1.0000x reference)
#include <cuda_runtime.h>
#include <math.h>
#include <stdint.h>

typedef unsigned long long u64;

// ---- scratch (static device globals; no allocation) ----
__device__ __align__(16) float d_XE[(size_t)64 * 32 * 10 * 1024];  // 80MB  [t][b][p][h]
__device__ __align__(16) float d_h[32 * 1024];                     // [b][h]
__device__ __align__(16) float d_c[32 * 1024];                     // [b][h]
__device__ __align__(16) float d_hT[1024 * 32];                    // [h][b]
__device__ __align__(16) float d_embT[1024 * 32];                  // [i][b]
__device__ __align__(16) float d_g2T[4096 * 32];                   // [j][b]
__device__ __align__(16) float d_hWhT[1024 * 32];                  // [h][b]
__device__ __align__(16) float d_WrecB[640 * 8192];                // 20MB blocked [tile][k][8]
__device__ __align__(16) float d_WihB[512 * 8192];                 // 16MB blocked [tile][k][8]
__device__ unsigned d_barc;                                        // grid barrier count
__device__ unsigned d_barg;                                        // grid barrier generation

// ---- f32x2 helpers ----
static __device__ __forceinline__ u64 dup2f(float a) {
    u64 r; asm("mov.b64 %0,{%1,%1};" : "=l"(r) : "f"(a)); return r;
}
static __device__ __forceinline__ void ffma2(u64& d, u64 a, u64 b) {
    asm("fma.rn.f32x2 %0,%1,%2,%0;" : "+l"(d) : "l"(a), "l"(b));
}
static __device__ __forceinline__ void unpack2(u64 v, float& a, float& b) {
    asm("mov.b64 {%0,%1},%2;" : "=f"(a), "=f"(b) : "l"(v));
}
static __device__ __forceinline__ float sigf(float x) { return 1.0f / (1.0f + expf(-x)); }

// ---- sub-block (256-thread) named barrier ----
static __device__ __forceinline__ void barsub(int nb) {
    asm volatile("bar.sync %0, %1;" :: "r"(nb), "r"(256) : "memory");
}

// ---- software grid barrier (all blocks resident; sense-reversing) ----
static __device__ __forceinline__ void gridbar() {
    __syncthreads();
    if (threadIdx.x == 0) {
        __threadfence();
        unsigned g = *(volatile unsigned*)&d_barg;
        if (atomicAdd(&d_barc, 1u) == gridDim.x - 1) {
            d_barc = 0;
            __threadfence();
            *(volatile unsigned*)&d_barg = g + 1;
        } else {
            while (*(volatile unsigned*)&d_barg == g) { }
            __threadfence();
        }
    }
    __syncthreads();
}

// ---- init: zero recurrent state ----
__global__ void k_init() {
    int i = blockIdx.x * blockDim.x + threadIdx.x;   // 512*256 = 131072
    d_g2T[i] = 0.0f;
    if (i < 32 * 1024) { d_c[i] = 0.0f; d_hWhT[i] = 0.0f; }
}

// ---- prep: blocked transpose of [Whh;Wh] -> WrecB[tile][k][s], j = tile*8+s ----
__global__ __launch_bounds__(256) void k_prep_rec(const float* __restrict__ Whh,
                                                  const float* __restrict__ Wh) {
    __shared__ __align__(16) float sm[32][36];
    const int tid = threadIdx.x;
    const int k0 = blockIdx.x * 32, jt = blockIdx.y;
    {
        int r = tid >> 3, c4 = (tid & 7) * 4;
        int j = jt * 32 + r;
        const float* src = (j < 4096) ? (Whh + (size_t)j * 1024) : (Wh + (size_t)(j - 4096) * 1024);
        *(float4*)&sm[r][c4] = *(const float4*)&src[k0 + c4];
    }
    __syncthreads();
    int kk = tid >> 3, s = tid & 7;
#pragma unroll
    for (int bji = 0; bji < 4; bji++) {
        d_WrecB[(size_t)(jt * 4 + bji) * 8192 + (k0 + kk) * 8 + s] = sm[bji * 8 + s][kk];
    }
}

// ---- prep: blocked transpose of Wih -> WihB[tile][k][s], s=(g,hh): j=g*1024+tile*2+hh ----
__global__ __launch_bounds__(256) void k_prep_ih(const float* __restrict__ Wih) {
    __shared__ __align__(16) float sm[32][36];
    const int tid = threadIdx.x;
    const int k0 = blockIdx.x * 32, grp = blockIdx.y;
    {
        int r = tid >> 3, c4 = (tid & 7) * 4;
        int g = r >> 3, bji = (r & 7) >> 1, hh = r & 1;
        int j = g * 1024 + (grp * 4 + bji) * 2 + hh;
        *(float4*)&sm[r][c4] = *(const float4*)&Wih[(size_t)j * 1024 + k0 + c4];
    }
    __syncthreads();
    int kk = tid >> 3, s = tid & 7;
    int g = s >> 1, hh = s & 1;
#pragma unroll
    for (int bji = 0; bji < 4; bji++) {
        d_WihB[(size_t)(grp * 4 + bji) * 8192 + (k0 + kk) * 8 + s] = sm[g * 8 + bji * 2 + hh][kk];
    }
}

// ---- K0: XE[r][h] = x_row[r] . Wx[h],  r=(t,b,p)  M=20480 N=1024 K=1024 (SIMT f32x2) ----
__global__ __launch_bounds__(256) void k_xe(const float* __restrict__ x,
                                            const float* __restrict__ Wx) {
    __shared__ __align__(16) float As[16][132];
    __shared__ __align__(16) float Bs[16][132];
    __shared__ int Abase[128];
    const int tid = threadIdx.x;
    const int n0 = blockIdx.x * 128, m0 = blockIdx.y * 128;
    if (tid < 128) {
        int r = m0 + tid, t = r / 320, rem = r - t * 320, b = rem / 10, p = rem - b * 10;
        Abase[tid] = ((b * 64 + t) * 10 + p) * 1024;
    }
    __syncthreads();
    const int tm = tid >> 4, tn = tid & 15;
    u64 acc[8][4];
#pragma unroll
    for (int i = 0; i < 8; i++)
#pragma unroll
        for (int j = 0; j < 4; j++) acc[i][j] = 0ull;

    for (int k0 = 0; k0 < 1024; k0 += 16) {
#pragma unroll
        for (int l = 0; l < 2; l++) {
            int ii = tid + 256 * l, m = ii >> 2, c = ii & 3;
            float4 va = *(const float4*)&x[Abase[m] + k0 + c * 4];
            As[c * 4 + 0][m] = va.x; As[c * 4 + 1][m] = va.y;
            As[c * 4 + 2][m] = va.z; As[c * 4 + 3][m] = va.w;
            float4 vb = *(const float4*)&Wx[(size_t)(n0 + m) * 1024 + k0 + c * 4];
            Bs[c * 4 + 0][m] = vb.x; Bs[c * 4 + 1][m] = vb.y;
            Bs[c * 4 + 2][m] = vb.z; Bs[c * 4 + 3][m] = vb.w;
        }
        __syncthreads();
#pragma unroll
        for (int kk = 0; kk < 16; kk++) {
            float4 alo = *(const float4*)&As[kk][tm * 8];
            float4 ahi = *(const float4*)&As[kk][tm * 8 + 4];
            ulonglong2 bl = *(const ulonglong2*)&Bs[kk][tn * 8];
            ulonglong2 bh = *(const ulonglong2*)&Bs[kk][tn * 8 + 4];
            float a8[8] = {alo.x, alo.y, alo.z, alo.w, ahi.x, ahi.y, ahi.z, ahi.w};
#pragma unroll
            for (int r = 0; r < 8; r++) {
                u64 ad = dup2f(a8[r]);
                ffma2(acc[r][0], ad, bl.x); ffma2(acc[r][1], ad, bl.y);
                ffma2(acc[r][2], ad, bh.x); ffma2(acc[r][3], ad, bh.y);
            }
        }
        __syncthreads();
    }
#pragma unroll
    for (int r = 0; r < 8; r++) {
        float o[8];
        unpack2(acc[r][0], o[0], o[1]); unpack2(acc[r][1], o[2], o[3]);
        unpack2(acc[r][2], o[4], o[5]); unpack2(acc[r][3], o[6], o[7]);
        size_t row = (size_t)(m0 + tm * 8 + r);
        *(float4*)&d_XE[row * 1024 + n0 + tn * 8]     = make_float4(o[0], o[1], o[2], o[3]);
        *(float4*)&d_XE[row * 1024 + n0 + tn * 8 + 4] = make_float4(o[4], o[5], o[6], o[7]);
    }
}

// ==== persistent recurrence kernel: 148 blocks x 512 threads, dyn smem 84KB ====
// per-sub (256 thr) smem: ws[1024][8] (32KB) + ps[8][8][32] (8KB) + gvs[8][32] (1KB)
#define SUB_BYTES 41984

__global__ __launch_bounds__(512) void k_loop(const float* __restrict__ x,
                                              const float* __restrict__ b_att,
                                              const float* __restrict__ v,
                                              const float* __restrict__ bih,
                                              const float* __restrict__ bhh,
                                              const float* __restrict__ Wfc,
                                              const float* __restrict__ bfc,
                                              float* __restrict__ out) {
    extern __shared__ __align__(16) char dsm[];
    __shared__ float s_att[10][17];
    __shared__ float s_al[10];
    const int tid = threadIdx.x, bid = blockIdx.x;
    const int subl = tid >> 8;            // 0/1 within block
    const int stid = tid & 255;
    const int nb = 1 + subl;              // named barrier id
    const int sub = bid * 2 + subl;       // global sub id, [0,296)
    float (*ws)[8]      = (float(*)[8])(dsm + subl * SUB_BYTES);
    float (*ps)[8][32]  = (float(*)[8][32])(dsm + subl * SUB_BYTES + 32768);
    float (*gvs)[32]    = (float(*)[32])(dsm + subl * SUB_BYTES + 32768 + 8192);
    const int w = stid >> 5, lane = stid & 31;

    for (int t = 0; t < 64; t++) {
        // ---- phase A: attention (blocks 0..31, one b each) ----
        if (bid < 32) {
            const int b = bid;
            const float* xe = d_XE + (size_t)(t * 32 + b) * 10240;
            float psc[10];
#pragma unroll
            for (int p = 0; p < 10; p++) psc[p] = 0.0f;
#pragma unroll
            for (int hh = 0; hh < 2; hh++) {
                int h = tid + hh * 512;
                float base = d_hWhT[h * 32 + b] + b_att[h];
                float vh = v[h];
#pragma unroll
                for (int p = 0; p < 10; p++)
                    psc[p] = fmaf(tanhf(xe[p * 1024 + h] + base), vh, psc[p]);
            }
            const int fl = tid & 31, fw = tid >> 5;
#pragma unroll
            for (int p = 0; p < 10; p++) {
                float s = psc[p];
#pragma unroll
                for (int off = 16; off; off >>= 1) s += __shfl_xor_sync(0xffffffffu, s, off);
                if (fl == 0) s_att[p][fw] = s;
            }
            __syncthreads();
            if (tid == 0) {
                float sc[10], mx = -1e30f;
#pragma unroll
                for (int p = 0; p < 10; p++) {
                    float s = 0.0f;
#pragma unroll
                    for (int q = 0; q < 16; q++) s += s_att[p][q];
                    sc[p] = s; mx = fmaxf(mx, s);
                }
                float den = 0.0f;
#pragma unroll
                for (int p = 0; p < 10; p++) { sc[p] = expf(sc[p] - mx); den += sc[p]; }
                float inv = 1.0f / den;
#pragma unroll
                for (int p = 0; p < 10; p++) s_al[p] = sc[p] * inv;
            }
            __syncthreads();
            float a[10];
#pragma unroll
            for (int p = 0; p < 10; p++) a[p] = s_al[p];
            const float* xb = x + (size_t)(b * 64 + t) * 10240;
#pragma unroll
            for (int hh = 0; hh < 2; hh++) {
                int i = tid + hh * 512;
                float s = 0.0f;
#pragma unroll
                for (int p = 0; p < 10; p++) s = fmaf(a[p], xb[p * 1024 + i], s);
                d_embT[i * 32 + b] = s;
            }
        }
        gridbar();

        // ---- phase B: gates GEMM + fused LSTM cell (512 tiles over 296 subs) ----
        for (int tl = sub; tl < 512; tl += 296) {
            const float4* wb = (const float4*)(d_WihB + (size_t)tl * 8192);
#pragma unroll
            for (int i = 0; i < 8; i++) ((float4*)ws)[stid + i * 256] = wb[stid + i * 256];
            barsub(nb);
            u64 acc[4] = {0ull, 0ull, 0ull, 0ull};
            const float* eb = d_embT + w * 128 * 32 + lane;
#pragma unroll 4
            for (int k = 0; k < 128; k++) {
                u64 ed = dup2f(eb[k * 32]);
                int kk = w * 128 + k;
                ulonglong2 w01 = *(const ulonglong2*)&ws[kk][0];
                ulonglong2 w23 = *(const ulonglong2*)&ws[kk][4];
                ffma2(acc[0], ed, w01.x); ffma2(acc[1], ed, w01.y);
                ffma2(acc[2], ed, w23.x); ffma2(acc[3], ed, w23.y);
            }
#pragma unroll
            for (int q = 0; q < 4; q++) {
                float a2, b2; unpack2(acc[q], a2, b2);
                ps[w][2 * q][lane] = a2; ps[w][2 * q + 1][lane] = b2;
            }
            barsub(nb);
            {
                const int s = w, b = lane;
                float r = 0.0f;
#pragma unroll
                for (int q = 0; q < 8; q++) r += ps[q][s][b];
                int g = s >> 1, hh = s & 1;
                int j = g * 1024 + tl * 2 + hh;
                r += d_g2T[j * 32 + b] + bih[j] + bhh[j];
                gvs[s][b] = r;
            }
            barsub(nb);
            if (stid < 64) {
                int b = stid >> 1, hh = stid & 1;
                int h = tl * 2 + hh;
                float iv = gvs[0 + hh][b], fv = gvs[2 + hh][b];
                float gv = gvs[4 + hh][b], ov = gvs[6 + hh][b];
                float c = d_c[b * 1024 + h];
                float cn = sigf(fv) * c + sigf(iv) * tanhf(gv);
                float hn = sigf(ov) * tanhf(cn);
                d_c[b * 1024 + h] = cn;
                d_h[b * 1024 + h] = hn;
                d_hT[h * 32 + b] = hn;
            }
        }
        gridbar();

        // ---- phase C: rec GEMM h @ [Whh;Wh]^T (640 tiles over 296 subs) ----
        if (t < 63) {
            for (int tl = sub; tl < 640; tl += 296) {
                const float4* wb = (const float4*)(d_WrecB + (size_t)tl * 8192);
#pragma unroll
                for (int i = 0; i < 8; i++) ((float4*)ws)[stid + i * 256] = wb[stid + i * 256];
                barsub(nb);
                u64 acc[4] = {0ull, 0ull, 0ull, 0ull};
                const float* eb = d_hT + w * 128 * 32 + lane;
#pragma unroll 4
                for (int k = 0; k < 128; k++) {
                    u64 ed = dup2f(eb[k * 32]);
                    int kk = w * 128 + k;
                    ulonglong2 w01 = *(const ulonglong2*)&ws[kk][0];
                    ulonglong2 w23 = *(const ulonglong2*)&ws[kk][4];
                    ffma2(acc[0], ed, w01.x); ffma2(acc[1], ed, w01.y);
                    ffma2(acc[2], ed, w23.x); ffma2(acc[3], ed, w23.y);
                }
#pragma unroll
                for (int q = 0; q < 4; q++) {
                    float a2, b2; unpack2(acc[q], a2, b2);
                    ps[w][2 * q][lane] = a2; ps[w][2 * q + 1][lane] = b2;
                }
                barsub(nb);
                {
                    const int s = w, b = lane;
                    float r = 0.0f;
#pragma unroll
                    for (int q = 0; q < 8; q++) r += ps[q][s][b];
                    int j = tl * 8 + s;
                    if (j < 4096) d_g2T[j * 32 + b] = r;
                    else          d_hWhT[(j - 4096) * 32 + b] = r;
                }
                barsub(nb);
            }
            gridbar();
        }
    }

    // ---- final FC (blocks 0..31) ----
    if (bid < 32 && tid < 256) {
        const int b = bid, fw = tid >> 5, fl = tid & 31;
        if (fw < 8) {
            const float* hr = d_h + b * 1024;
            const float* wr = Wfc + fw * 1024;
            float s = 0.0f;
            for (int i = fl * 4; i < 1024; i += 128) {
                float4 hv = *(const float4*)&hr[i];
                float4 wv = *(const float4*)&wr[i];
                s = fmaf(hv.x, wv.x, s); s = fmaf(hv.y, wv.y, s);
                s = fmaf(hv.z, wv.z, s); s = fmaf(hv.w, wv.w, s);
            }
#pragma unroll
            for (int off = 16; off; off >>= 1) s += __shfl_xor_sync(0xffffffffu, s, off);
            if (fl == 0) out[b * 8 + fw] = s + bfc[fw];
        }
    }
}

extern "C" void kernel_launch(void* const* d_in, const int* in_sizes, int n_in,
                              void* d_out, int out_size) {
    const float* x     = (const float*)d_in[0];
    const float* Wx    = (const float*)d_in[1];
    const float* Wh    = (const float*)d_in[2];
    const float* b_att = (const float*)d_in[3];
    const float* v     = (const float*)d_in[4];
    const float* Wih   = (const float*)d_in[5];
    const float* Whh   = (const float*)d_in[6];
    const float* bih   = (const float*)d_in[7];
    const float* bhh   = (const float*)d_in[8];
    const float* Wfc   = (const float*)d_in[9];
    const float* bfc   = (const float*)d_in[10];
    float* out = (float*)d_out;

    static int attr_set = 0;
    if (!attr_set) {
        cudaFuncSetAttribute(k_loop, cudaFuncAttributeMaxDynamicSharedMemorySize,
                             2 * SUB_BYTES);
        attr_set = 1;
    }

    k_init<<<512, 256>>>();
    k_prep_rec<<<dim3(32, 160), 256>>>(Whh, Wh);
    k_prep_ih<<<dim3(32, 128), 256>>>(Wih);
    k_xe<<<dim3(8, 160), 256>>>(x, Wx);
    k_loop<<<148, 512, 2 * SUB_BYTES>>>(x, b_att, v, bih, bhh, Wfc, bfc, out);
}